// round 3
// baseline (speedup 1.0000x reference)
#include <cuda_runtime.h>
#include <cstdint>

// Problem constants
#define NB   4
#define IC   3
#define OC   16
#define IDIM 128
#define ODIM 127
#define H_STR   128
#define D_STR   (128*128)         // 16384
#define C_STR   (128*128*128)     // 2097152
#define O_HSTR  127
#define O_DSTR  (127*127)         // 16129
#define O_CSTR  (127*127*127)     // 2048383

typedef unsigned long long ull;

__device__ float2 g_fw[24][16];   // [tap = ic*8+kd*4+kh*2+kw][oc], value duplicated (w,w)
__device__ float2 g_fb[16];       // duplicated (b,b)

__device__ __forceinline__ ull fma2(ull a, ull b, ull c) {
    ull d;
    asm("fma.rn.f32x2 %0, %1, %2, %3;" : "=l"(d) : "l"(a), "l"(b), "l"(c));
    return d;
}
__device__ __forceinline__ ull pack2(float lo, float hi) {
    ull d;
    asm("mov.b64 %0, {%1, %2};" : "=l"(d) : "f"(lo), "f"(hi));
    return d;
}
__device__ __forceinline__ float2 unpack2(ull v) {
    float2 r;
    asm("mov.b64 {%0, %1}, %2;" : "=f"(r.x), "=f"(r.y) : "l"(v));
    return r;
}

// Fold ConvTranspose(k3,s2,p1)+AvgPool(2) -> 2x2x2 conv weight, with scales.
// Folded axis index 0 <- original taps {1,2} summed ; index 1 <- tap {0}.
__global__ void prep_kernel(const float* __restrict__ cw,
                            const float* __restrict__ cb,
                            const float* __restrict__ eb) {
    int t = threadIdx.x;
    if (t >= 24 * 16) return;
    int oc  = t & 15;
    int tap = t >> 4;                 // 0..23
    int kw = tap & 1, kh = (tap >> 1) & 1, kd = (tap >> 2) & 1, ic = tap >> 3;
    int dlo = kd ? 0 : 1, dhi = kd ? 1 : 3;
    int hlo = kh ? 0 : 1, hhi = kh ? 1 : 3;
    int wlo = kw ? 0 : 1, whi = kw ? 1 : 3;
    const float* w = cw + (ic * 16 + oc) * 27;   // cw layout (ic, oc, 3,3,3)
    float s = 0.f;
    for (int i = dlo; i < dhi; i++)
        for (int j = hlo; j < hhi; j++)
            for (int k = wlo; k < whi; k++)
                s += w[i * 9 + j * 3 + k];
    s *= 0.0625f;                                 // SCALE1*SCALE2*0.125
    g_fw[tap][oc] = make_float2(s, s);
    if (t < 16) {
        float b = cb[t] * 0.5f + eb[t];          // (cb*SCALE1 + ext)*SCALE2
        g_fb[t] = make_float2(b, b);
    }
}

// Cyclic-by-32 w mapping: lane covers w = lane + {0,32,64,96}; pairs
// (chunk0,chunk1) and (chunk2,chunk3) as f32x2. All LDG/STG fully coalesced.
// Two sequential oc-half passes (8 oc each) to keep regs low.
// Block = 32(lane) x 8(oh). Grid = (16 oh-tiles, 127 od, 4 n).
__global__ void __launch_bounds__(256, 3)
conv_main(const float* __restrict__ x, float* __restrict__ out) {
    // [half][rb = ic*4+kd*2+kh][oc] : (w_kw0, w_kw0, w_kw1, w_kw1)
    __shared__ float4 smw[2][12][8];
    __shared__ float2 smb[16];

    int tid = threadIdx.y * 32 + threadIdx.x;
    for (int i = tid; i < 2 * 12 * 8; i += 256) {
        int half = i / 96;
        int rb   = (i % 96) / 8;
        int oc   = i & 7;
        int ic = rb / 4, kd = (rb / 2) & 1, kh = rb & 1;
        int ocg = half * 8 + oc;
        float w0 = g_fw[ic * 8 + kd * 4 + kh * 2 + 0][ocg].x;
        float w1 = g_fw[ic * 8 + kd * 4 + kh * 2 + 1][ocg].x;
        smw[half][rb][oc] = make_float4(w0, w0, w1, w1);
    }
    if (tid < 16) smb[tid] = g_fb[tid];
    __syncthreads();

    int lane = threadIdx.x;
    int oh = blockIdx.x * 8 + threadIdx.y;
    if (oh >= ODIM) return;
    int od = blockIdx.y;
    int n  = blockIdx.z;
    bool lastlane = (lane == 31);          // chunk3 output w=127 invalid

    const float* xn = x + (size_t)n * IC * C_STR
                        + (size_t)od * D_STR
                        + (size_t)oh * H_STR + lane;
    float* ob = out + (size_t)n * OC * O_CSTR
                    + (size_t)od * O_DSTR
                    + (size_t)oh * O_HSTR + lane;

#pragma unroll
    for (int half = 0; half < 2; half++) {
        ull acc[8][2];
#pragma unroll
        for (int oc = 0; oc < 8; oc++) {
            ull b = *(const ull*)&smb[half * 8 + oc];
            acc[oc][0] = b;
            acc[oc][1] = b;
        }

#pragma unroll
        for (int ic = 0; ic < IC; ic++) {
#pragma unroll
            for (int kd = 0; kd < 2; kd++) {
#pragma unroll
                for (int kh = 0; kh < 2; kh++) {
                    const float* row = xn + (size_t)ic * C_STR
                                          + (size_t)kd * D_STR
                                          + (size_t)kh * H_STR;
                    float v0 = row[0],  v1 = row[32], v2 = row[64], v3 = row[96];
                    float u0 = row[1],  u1 = row[33], u2 = row[65];
                    float u3 = lastlane ? 0.f : row[97];
                    ull pA = pack2(v0, v1);
                    ull pB = pack2(v2, v3);
                    ull qA = pack2(u0, u1);
                    ull qB = pack2(u2, u3);
                    int rb = ic * 4 + kd * 2 + kh;
#pragma unroll
                    for (int oc = 0; oc < 8; oc++) {
                        const ulonglong2* wp =
                            (const ulonglong2*)&smw[half][rb][oc];
                        ulonglong2 w = *wp;                 // one LDS.128
                        acc[oc][0] = fma2(pA, w.x, acc[oc][0]);
                        acc[oc][1] = fma2(pB, w.x, acc[oc][1]);
                        acc[oc][0] = fma2(qA, w.y, acc[oc][0]);
                        acc[oc][1] = fma2(qB, w.y, acc[oc][1]);
                    }
                }
            }
        }

#pragma unroll
        for (int oc = 0; oc < 8; oc++) {
            float2 a = unpack2(acc[oc][0]);
            float2 b = unpack2(acc[oc][1]);
            float* o = ob + (size_t)(half * 8 + oc) * O_CSTR;
            __stcs(o,      a.x);
            __stcs(o + 32, a.y);
            __stcs(o + 64, b.x);
            if (!lastlane) __stcs(o + 96, b.y);
        }
    }
}

extern "C" void kernel_launch(void* const* d_in, const int* in_sizes, int n_in,
                              void* d_out, int out_size) {
    const float* x  = (const float*)d_in[0];
    const float* cw = (const float*)d_in[1];
    const float* cb = (const float*)d_in[2];
    const float* eb = (const float*)d_in[3];
    float* out = (float*)d_out;

    prep_kernel<<<1, 24 * 16>>>(cw, cb, eb);

    dim3 block(32, 8, 1);
    dim3 grid(16, ODIM, NB);    // 16 oh-tiles of 8, 127 od, 4 batches
    conv_main<<<grid, block>>>(x, out);
}

// round 4
// speedup vs baseline: 1.6120x; 1.6120x over previous
#include <cuda_runtime.h>
#include <cstdint>

#define NB   4
#define IC   3
#define OC   16
#define ODIM 127
#define H_STR   128
#define D_STR   (128*128)
#define C_STR   (128*128*128)
#define O_HSTR  127
#define O_DSTR  (127*127)
#define O_CSTR  (127*127*127)

typedef unsigned long long ull;

// Packed folded weights: [half][ic][kh][kd][kw][quad] -> float4 of 4 oc scalars
__device__ float4 g_pw[2][3][2][2][2][2];
__device__ float2 g_fb[16];

__device__ __forceinline__ ull fma2(ull a, ull b, ull c) {
    ull d;
    asm("fma.rn.f32x2 %0, %1, %2, %3;" : "=l"(d) : "l"(a), "l"(b), "l"(c));
    return d;
}
__device__ __forceinline__ ull pack2(float lo, float hi) {
    ull d;
    asm("mov.b64 %0, {%1, %2};" : "=l"(d) : "f"(lo), "f"(hi));
    return d;
}
__device__ __forceinline__ float2 unpack2(ull v) {
    float2 r;
    asm("mov.b64 {%0, %1}, %2;" : "=f"(r.x), "=f"(r.y) : "l"(v));
    return r;
}

// Fold ConvTranspose(k3,s2,p1)+AvgPool(2) -> 2x2x2 conv, with scales.
__global__ void prep_kernel(const float* __restrict__ cw,
                            const float* __restrict__ cb,
                            const float* __restrict__ eb) {
    int t = threadIdx.x;
    if (t >= 384) return;
    // t -> (half, ic, kh, kd, kw, quad, e)
    int e    = t & 3;
    int quad = (t >> 2) & 1;
    int kw   = (t >> 3) & 1;
    int kd   = (t >> 4) & 1;
    int kh   = (t >> 5) & 1;
    int ic   = (t >> 6) % 3;
    int half = t / 192;
    int oc = half * 8 + quad * 4 + e;

    int dlo = kd ? 0 : 1, dhi = kd ? 1 : 3;
    int hlo = kh ? 0 : 1, hhi = kh ? 1 : 3;
    int wlo = kw ? 0 : 1, whi = kw ? 1 : 3;
    const float* w = cw + (ic * 16 + oc) * 27;   // (ic, oc, 3,3,3)
    float s = 0.f;
    for (int i = dlo; i < dhi; i++)
        for (int j = hlo; j < hhi; j++)
            for (int k = wlo; k < whi; k++)
                s += w[i * 9 + j * 3 + k];
    s *= 0.0625f;                                // SCALE1*SCALE2*0.125
    ((float*)&g_pw[half][ic][kh][kd][kw][quad])[e] = s;
    if (t < 16) {
        float b = cb[t] * 0.5f + eb[t];
        g_fb[t] = make_float2(b, b);
    }
}

// Thread: 2 od x 4 w-chunks (cyclic by 32) x 8 oc (per half pass) at one (n,oh).
// Block = 32(lane) x 8(oh). Grid = (16 oh-tiles, 64 od-pairs, 4 n).
__global__ void __launch_bounds__(256, 2)
conv_main(const float* __restrict__ x, float* __restrict__ out) {
    __shared__ float4 smw[2][3][2][2][2][2];
    __shared__ float2 smb[16];

    int tid = threadIdx.y * 32 + threadIdx.x;
    {
        const float4* gw = (const float4*)g_pw;
        float4* sw = (float4*)smw;
        if (tid < 96) sw[tid] = gw[tid];
        if (tid < 16) smb[tid] = g_fb[tid];
    }
    __syncthreads();

    int lane = threadIdx.x;
    int oh = blockIdx.x * 8 + threadIdx.y;
    if (oh >= ODIM) return;
    int od0 = blockIdx.y * 2;
    int n   = blockIdx.z;
    bool two = (od0 + 1 < ODIM);      // od0==126 -> single od
    bool lastlane = (lane == 31);

    const float* xb = x + (size_t)n * IC * C_STR
                        + (size_t)od0 * D_STR
                        + (size_t)oh * H_STR + lane;
    float* ob = out + (size_t)n * OC * O_CSTR
                    + (size_t)od0 * O_DSTR
                    + (size_t)oh * O_HSTR + lane;

#pragma unroll 1
    for (int half = 0; half < 2; half++) {
        ull acc[2][8][2];
#pragma unroll
        for (int oc = 0; oc < 8; oc++) {
            ull b = *(const ull*)&smb[half * 8 + oc];
            acc[0][oc][0] = b; acc[0][oc][1] = b;
            acc[1][oc][0] = b; acc[1][oc][1] = b;
        }

#pragma unroll
        for (int ic = 0; ic < IC; ic++) {
#pragma unroll
            for (int kh = 0; kh < 2; kh++) {
                const float* rp = xb + (size_t)ic * C_STR + (size_t)kh * H_STR;

                // Load 3 od-rows (od0, od0+1, od0+2), 4 coalesced chunks each.
                float v[3][4];
#pragma unroll
                for (int j = 0; j < 3; j++) {
                    if (j == 2 && !two) {
                        v[2][0] = v[2][1] = v[2][2] = v[2][3] = 0.f;
                    } else {
                        const float* r = rp + (size_t)j * D_STR;
                        v[j][0] = r[0];  v[j][1] = r[32];
                        v[j][2] = r[64]; v[j][3] = r[96];
                    }
                }

                // u[j][c] = row_j[32c + lane + 1] via shuffles (off L1 path)
                ull pA[3], pB[3], qA[3], qB[3];
#pragma unroll
                for (int j = 0; j < 3; j++) {
                    float u0 = __shfl_down_sync(0xffffffffu, v[j][0], 1);
                    float u1 = __shfl_down_sync(0xffffffffu, v[j][1], 1);
                    float u2 = __shfl_down_sync(0xffffffffu, v[j][2], 1);
                    float u3 = __shfl_down_sync(0xffffffffu, v[j][3], 1); // lane31 don't-care
                    float b0 = __shfl_sync(0xffffffffu, v[j][1], 0);
                    float b1 = __shfl_sync(0xffffffffu, v[j][2], 0);
                    float b2 = __shfl_sync(0xffffffffu, v[j][3], 0);
                    if (lastlane) { u0 = b0; u1 = b1; u2 = b2; }
                    pA[j] = pack2(v[j][0], v[j][1]);
                    pB[j] = pack2(v[j][2], v[j][3]);
                    qA[j] = pack2(u0, u1);
                    qB[j] = pack2(u2, u3);
                }

#pragma unroll
                for (int kd = 0; kd < 2; kd++) {
                    float4 w0a = smw[half][ic][kh][kd][0][0]; // kw=0, oc 0-3
                    float4 w0b = smw[half][ic][kh][kd][0][1]; // kw=0, oc 4-7
                    float4 w1a = smw[half][ic][kh][kd][1][0]; // kw=1, oc 0-3
                    float4 w1b = smw[half][ic][kh][kd][1][1]; // kw=1, oc 4-7
                    const float* f0 = (const float*)&w0a;
                    const float* f1 = (const float*)&w1a;
#pragma unroll
                    for (int oc = 0; oc < 8; oc++) {
                        float ws0 = (oc < 4) ? f0[oc] : ((const float*)&w0b)[oc - 4];
                        float ws1 = (oc < 4) ? f1[oc] : ((const float*)&w1b)[oc - 4];
                        ull W0 = pack2(ws0, ws0);
                        ull W1 = pack2(ws1, ws1);
                        acc[0][oc][0] = fma2(pA[kd],     W0, acc[0][oc][0]);
                        acc[0][oc][1] = fma2(pB[kd],     W0, acc[0][oc][1]);
                        acc[0][oc][0] = fma2(qA[kd],     W1, acc[0][oc][0]);
                        acc[0][oc][1] = fma2(qB[kd],     W1, acc[0][oc][1]);
                        acc[1][oc][0] = fma2(pA[kd + 1], W0, acc[1][oc][0]);
                        acc[1][oc][1] = fma2(pB[kd + 1], W0, acc[1][oc][1]);
                        acc[1][oc][0] = fma2(qA[kd + 1], W1, acc[1][oc][0]);
                        acc[1][oc][1] = fma2(qB[kd + 1], W1, acc[1][oc][1]);
                    }
                }
            }
        }

#pragma unroll
        for (int oc = 0; oc < 8; oc++) {
            float* o0 = ob + (size_t)(half * 8 + oc) * O_CSTR;
            float2 a = unpack2(acc[0][oc][0]);
            float2 b = unpack2(acc[0][oc][1]);
            __stcs(o0,      a.x);
            __stcs(o0 + 32, a.y);
            __stcs(o0 + 64, b.x);
            if (!lastlane) __stcs(o0 + 96, b.y);
            if (two) {
                float* o1 = o0 + O_DSTR;
                float2 c = unpack2(acc[1][oc][0]);
                float2 d = unpack2(acc[1][oc][1]);
                __stcs(o1,      c.x);
                __stcs(o1 + 32, c.y);
                __stcs(o1 + 64, d.x);
                if (!lastlane) __stcs(o1 + 96, d.y);
            }
        }
    }
}

extern "C" void kernel_launch(void* const* d_in, const int* in_sizes, int n_in,
                              void* d_out, int out_size) {
    const float* x  = (const float*)d_in[0];
    const float* cw = (const float*)d_in[1];
    const float* cb = (const float*)d_in[2];
    const float* eb = (const float*)d_in[3];
    float* out = (float*)d_out;

    prep_kernel<<<1, 384>>>(cw, cb, eb);

    dim3 block(32, 8, 1);
    dim3 grid(16, 64, NB);    // 16 oh-tiles, 64 od-pairs, 4 batches
    conv_main<<<grid, block>>>(x, out);
}